// round 16
// baseline (speedup 1.0000x reference)
#include <cuda_runtime.h>

#define B_CHAIN 16384
#define S_SIDE 15
#define NATM (1 + B_CHAIN + B_CHAIN * S_SIDE)   // 262145

#define NBB 32            // backbone scan blocks
#define TPB 512           // threads per backbone block (NBB*TPB == B_CHAIN)
#define NWARP (TPB / 32)  // 16

// Scratch (device globals; no runtime allocation allowed).
// Transforms stored as 3 float4 rows (row-major 3x4; .w = translation).
__device__ float4 g_H4[3 * NATM];         // per-node transforms
__device__ float4 g_loc4[3 * B_CHAIN];    // block-local backbone scans
__device__ float  g_agg[NBB * 12];        // backbone block aggregates (AoS)

struct Aff { float m[12]; };  // row-major 3x4 affine; m[r*4+3] = translation

__device__ __forceinline__ Aff aff_identity() {
    Aff I;
#pragma unroll
    for (int k = 0; k < 12; ++k) I.m[k] = 0.0f;
    I.m[0] = I.m[5] = I.m[10] = 1.0f;
    return I;
}

__device__ __forceinline__ Aff aff_mul(const Aff& A, const Aff& B) {
    Aff C;
#pragma unroll
    for (int r = 0; r < 3; ++r) {
#pragma unroll
        for (int c = 0; c < 4; ++c) {
            float s = A.m[r*4+0] * B.m[0*4+c]
                    + A.m[r*4+1] * B.m[1*4+c]
                    + A.m[r*4+2] * B.m[2*4+c];
            if (c == 3) s += A.m[r*4+3];
            C.m[r*4+c] = s;
        }
    }
    return C;
}

__device__ __forceinline__ Aff shfl_up_aff(const Aff& a, int delta, int width) {
    Aff r;
#pragma unroll
    for (int k = 0; k < 12; ++k)
        r.m[k] = __shfl_up_sync(0xffffffffu, a.m[k], delta, width);
    return r;
}

__device__ __forceinline__ Aff shfl_down_aff(const Aff& a, int delta) {
    Aff r;
#pragma unroll
    for (int k = 0; k < 12; ++k)
        r.m[k] = __shfl_down_sync(0xffffffffu, a.m[k], delta, 32);
    return r;
}

__device__ __forceinline__ void store_aff4(float4* base, int stride, int n, const Aff& A) {
#pragma unroll
    for (int r = 0; r < 3; ++r)
        base[r * stride + n] = make_float4(A.m[r*4+0], A.m[r*4+1], A.m[r*4+2], A.m[r*4+3]);
}

__device__ __forceinline__ Aff load_aff4(const float4* base, int stride, int n) {
    Aff A;
#pragma unroll
    for (int r = 0; r < 3; ++r) {
        float4 v = base[r * stride + n];
        A.m[r*4+0] = v.x; A.m[r*4+1] = v.y; A.m[r*4+2] = v.z; A.m[r*4+3] = v.w;
    }
    return A;
}

// Per-node transform, closed forms.
// doftype==2 (bond): Rx(d0) Rz(d1) T(d2,0,0) Rx(d3)
// doftype==1 (jump): T(d0,d1,d2) Rz(d5) Ry(d4) Rx(d3)
// doftype==0: identity
// PRECISE=true (backbone): libm sincosf — error compounds over 16384 products.
// PRECISE=false (sides): __sincosf MUFU — 15-deep products, error ~1e-6.
template <bool PRECISE>
__device__ __forceinline__ Aff build_ht_from(int dt, float4 d, int n,
                                             const float* __restrict__ full_dofs) {
    if (dt == 0) return aff_identity();
    Aff H;
    if (dt == 2) {
        float sa, ca, sb, cb, sc, cc;
        if (PRECISE) { sincosf(d.x, &sa, &ca); sincosf(d.y, &sb, &cb); sincosf(d.w, &sc, &cc); }
        else         { __sincosf(d.x, &sa, &ca); __sincosf(d.y, &sb, &cb); __sincosf(d.w, &sc, &cc); }
        float x = d.z;
        H.m[0] = cb;      H.m[1]  = -sb * cc;             H.m[2]  = sb * sc;               H.m[3]  = cb * x;
        H.m[4] = ca * sb; H.m[5]  = ca * cb * cc - sa*sc; H.m[6]  = -ca * cb * sc - sa*cc; H.m[7]  = ca * sb * x;
        H.m[8] = sa * sb; H.m[9]  = sa * cb * cc + ca*sc; H.m[10] = -sa * cb * sc + ca*cc; H.m[11] = sa * sb * x;
    } else {
        float a = d.w;
        float b = full_dofs[n * 9 + 4];
        float g = full_dofs[n * 9 + 5];
        float sa, ca, sb, cb, sg, cg;
        if (PRECISE) { sincosf(a, &sa, &ca); sincosf(b, &sb, &cb); sincosf(g, &sg, &cg); }
        else         { __sincosf(a, &sa, &ca); __sincosf(b, &sb, &cb); __sincosf(g, &sg, &cg); }
        H.m[0] = cg * cb; H.m[1]  = cg * sb * sa - sg * ca; H.m[2]  = cg * sb * ca + sg * sa; H.m[3]  = d.x;
        H.m[4] = sg * cb; H.m[5]  = sg * sb * sa + cg * ca; H.m[6]  = sg * sb * ca - cg * sa; H.m[7]  = d.y;
        H.m[8] = -sb;     H.m[9]  = cb * sa;                H.m[10] = cb * ca;                H.m[11] = d.z;
    }
    return H;
}

// ============ K1: build ALL node transforms at full occupancy ================
__global__ void __launch_bounds__(256)
k1_build(const float4* __restrict__ dofs4,
         const float* __restrict__ full_dofs,
         const int* __restrict__ doftype) {
    int n = blockIdx.x * 256 + threadIdx.x + 1;   // node 1..NATM-1
    if (n >= NATM) return;
    int dt = doftype[n];
    float4 d = dofs4[n - 1];
    Aff H;
    if (n <= B_CHAIN) H = build_ht_from<true >(dt, d, n, full_dofs);  // backbone: precise
    else              H = build_ht_from<false>(dt, d, n, full_dofs);  // sides: fast
    store_aff4(g_H4, NATM, n, H);
}

// ============ K2: backbone block-local scans (reads g_H4, no sincos) =========
__global__ void __launch_bounds__(TPB)
k2_scan() {
    const int t    = threadIdx.x;
    const int bid  = blockIdx.x;
    const int item = bid * TPB + t;
    const int n    = item + 1;        // backbone node 1..16384
    const int lane = t & 31;
    const int warp = t >> 5;

    __shared__ float s_agg[NWARP][12];
    __shared__ float s_inc[NWARP][12];

    Aff M = load_aff4(g_H4, NATM, n);

    // warp shuffle inclusive scan
#pragma unroll
    for (int d = 1; d < 32; d <<= 1) {
        Aff P = shfl_up_aff(M, d, 32);
        if (lane >= d) M = aff_mul(P, M);
    }
    if (lane == 31) {
#pragma unroll
        for (int k = 0; k < 12; ++k) s_agg[warp][k] = M.m[k];
    }
    __syncthreads();

    if (warp == 0) {
        Aff A = aff_identity();
        if (lane < NWARP) {
#pragma unroll
            for (int k = 0; k < 12; ++k) A.m[k] = s_agg[lane][k];
        }
#pragma unroll
        for (int d = 1; d < NWARP; d <<= 1) {
            Aff P = shfl_up_aff(A, d, NWARP);
            if (lane >= d && lane < NWARP) A = aff_mul(P, A);
        }
        if (lane < NWARP) {
#pragma unroll
            for (int k = 0; k < 12; ++k) s_inc[lane][k] = A.m[k];
        }
        if (lane == NWARP - 1) {
#pragma unroll
            for (int k = 0; k < 12; ++k) g_agg[bid * 12 + k] = A.m[k];
        }
    }
    __syncthreads();

    if (warp > 0) {
        Aff W;
#pragma unroll
        for (int k = 0; k < 12; ++k) W.m[k] = s_inc[warp - 1][k];
        M = aff_mul(W, M);
    }
    store_aff4(g_loc4, B_CHAIN, item, M);
}

// ============ K3: apply prefixes + side chains + scatter ======================
// 256 threads/block = 32 chains x 8 lanes. 512 blocks. chunk = backbone block.
__global__ void __launch_bounds__(256)
k3_apply(const int* __restrict__ kin_id,
         float* __restrict__ out) {
    const int t     = threadIdx.x;
    const int bid   = blockIdx.x;
    const int chain = bid * 32 + (t >> 3);   // 0..B_CHAIN-1
    const int l     = t & 7;                 // lane within chain
    const int chunk = bid >> 4;              // backbone block id (0..31)

    __shared__ float s_pre[12];              // exclusive prefix of this chunk

    // warp 0 computes E = agg[0] * ... * agg[chunk-1] (ordered tree reduce)
    if (t < 32) {
        Aff V = aff_identity();
        if (t < chunk) {
#pragma unroll
            for (int k = 0; k < 12; ++k) V.m[k] = g_agg[t * 12 + k];
        }
#pragma unroll
        for (int d = 1; d < 32; d <<= 1) {
            Aff Hh = shfl_down_aff(V, d);
            if ((t & (2 * d - 1)) == 0) V = aff_mul(V, Hh);
        }
        if (t == 0) {
#pragma unroll
            for (int k = 0; k < 12; ++k) s_pre[k] = V.m[k];
        }
    }
    __syncthreads();

    // G = global transform of backbone node chain+1
    Aff G;
    {
        Aff E;
#pragma unroll
        for (int k = 0; k < 12; ++k) E.m[k] = s_pre[k];
        Aff L = load_aff4(g_loc4, B_CHAIN, chain);
        G = aff_mul(E, L);
    }

    // lane 0 writes the backbone coordinate
    if (l == 0) {
        int o = kin_id[chain + 1];
        out[o * 3 + 0] = G.m[3];
        out[o * 3 + 1] = G.m[7];
        out[o * 3 + 2] = G.m[11];
    }

    // side chain: lane l<7 covers side positions {2l, 2l+1}; lane 7 covers {14}
    const int nb    = 1 + B_CHAIN + chain * S_SIDE;
    const int n0    = nb + 2 * l;
    const bool has2 = (l < 7);

    Aff S = load_aff4(g_H4, NATM, n0);
    float t0x = S.m[3], t0y = S.m[7], t0z = S.m[11];

    if (has2) {
        Aff H1 = load_aff4(g_H4, NATM, n0 + 1);
        S = aff_mul(S, H1);
    }

    // width-8 inclusive scan of segment products
#pragma unroll
    for (int d = 1; d < 8; d <<= 1) {
        Aff P = shfl_up_aff(S, d, 8);
        if (l >= d) S = aff_mul(P, S);
    }
    // last node of this lane's segment: coord = R(G)*t(S_inc) + t(G)
    {
        int nlast = has2 ? (n0 + 1) : n0;
        int o = kin_id[nlast];
        float cx = G.m[0]*S.m[3] + G.m[1]*S.m[7] + G.m[2]*S.m[11]  + G.m[3];
        float cy = G.m[4]*S.m[3] + G.m[5]*S.m[7] + G.m[6]*S.m[11]  + G.m[7];
        float cz = G.m[8]*S.m[3] + G.m[9]*S.m[7] + G.m[10]*S.m[11] + G.m[11];
        out[o * 3 + 0] = cx;
        out[o * 3 + 1] = cy;
        out[o * 3 + 2] = cz;
    }
    // first node of a 2-node segment: coord = (G * E_side) applied to t(H0)
    if (has2) {
        Aff E = shfl_up_aff(S, 1, 8);
        if (l == 0) E = aff_identity();
        Aff P = aff_mul(G, E);
        int o = kin_id[n0];
        float cx = P.m[0]*t0x + P.m[1]*t0y + P.m[2]*t0z  + P.m[3];
        float cy = P.m[4]*t0x + P.m[5]*t0y + P.m[6]*t0z  + P.m[7];
        float cz = P.m[8]*t0x + P.m[9]*t0y + P.m[10]*t0z + P.m[11];
        out[o * 3 + 0] = cx;
        out[o * 3 + 1] = cy;
        out[o * 3 + 2] = cz;
    }
}

// ---------------- launch -----------------------------------------------------
extern "C" void kernel_launch(void* const* d_in, const int* in_sizes, int n_in,
                              void* d_out, int out_size) {
    // metadata order: dofs, full_dofs, node_idx, dof_idx, doftype,
    //                 gen0_nodes, gen1_nodes, gen1_parents, kin_id
    const float4* dofs4     = (const float4*)d_in[0];
    const float*  full_dofs = (const float*)d_in[1];
    const int*    doftype   = (const int*)d_in[4];
    const int*    kin_id    = (const int*)d_in[8];
    float* out = (float*)d_out;

    k1_build<<<(NATM - 1 + 255) / 256, 256>>>(dofs4, full_dofs, doftype);
    k2_scan<<<NBB, TPB>>>();
    k3_apply<<<B_CHAIN / 32, 256>>>(kin_id, out);
}